// round 13
// baseline (speedup 1.0000x reference)
#include <cuda_runtime.h>
#include <cuda_bf16.h>
#include <math.h>
#include <stdint.h>

#define N_NODES 10000
#define N_EDGES 80000
#define IN_DIM  1024
#define HID     4096
#define OUT_DIM 256

// ---------------------------------------------------------------------------
// Scratch (device globals)
// ---------------------------------------------------------------------------
__device__ __align__(16) __nv_bfloat16 g_agg1b[(size_t)N_NODES * IN_DIM];   // 20 MB
__device__ __align__(16) __nv_bfloat16 g_xb[(size_t)N_NODES * IN_DIM];      // 20 MB
__device__ __align__(16) __nv_bfloat16 g_h[(size_t)N_NODES * HID];          // 80 MB
__device__ __align__(16) float g_t2[(size_t)N_NODES * OUT_DIM];             // 10 MB
__device__ __align__(16) __nv_bfloat16 g_w1lb[(size_t)HID * IN_DIM];        // 8 MB
__device__ __align__(16) __nv_bfloat16 g_w1rb[(size_t)HID * IN_DIM];        // 8 MB
__device__ __align__(16) __nv_bfloat16 g_w2lb[(size_t)OUT_DIM * HID];       // 2 MB
__device__ __align__(16) __nv_bfloat16 g_w2rb[(size_t)OUT_DIM * HID];       // 2 MB
// CSR
__device__ int g_rowptr[N_NODES + 1];
__device__ int g_csrc[N_EDGES];

// ---------------------------------------------------------------------------
// MMA / async-copy helpers
// ---------------------------------------------------------------------------
__device__ __forceinline__ void mma_bf16(float c[4],
        uint32_t a0, uint32_t a1, uint32_t a2, uint32_t a3,
        uint32_t b0, uint32_t b1) {
    asm volatile(
        "mma.sync.aligned.m16n8k16.row.col.f32.bf16.bf16.f32 "
        "{%0,%1,%2,%3},{%4,%5,%6,%7},{%8,%9},{%0,%1,%2,%3};"
        : "+f"(c[0]), "+f"(c[1]), "+f"(c[2]), "+f"(c[3])
        : "r"(a0), "r"(a1), "r"(a2), "r"(a3), "r"(b0), "r"(b1));
}
__device__ __forceinline__ void ldsm_x4(uint32_t r[4], uint32_t addr) {
    asm volatile("ldmatrix.sync.aligned.m8n8.x4.shared.b16 {%0,%1,%2,%3}, [%4];"
                 : "=r"(r[0]), "=r"(r[1]), "=r"(r[2]), "=r"(r[3]) : "r"(addr));
}
__device__ __forceinline__ void cp_async16(uint32_t smem, const void* g, bool valid) {
    int sz = valid ? 16 : 0;
    asm volatile("cp.async.cg.shared.global [%0], [%1], 16, %2;\n"
                 :: "r"(smem), "l"(g), "r"(sz));
}
__device__ __forceinline__ void cp_commit() { asm volatile("cp.async.commit_group;\n"); }
template<int W> __device__ __forceinline__ void cp_wait() {
    asm volatile("cp.async.wait_group %0;\n" :: "n"(W));
}

// ---------------------------------------------------------------------------
// BF16 tensor-core GEMM:  C[M,N] = A[M,K] @ W[N,K]^T   (A,W bf16; C fp32/bf16)
// Template MI: warp m-tile = MI*16, BM = 32*MI (MI=4 -> 128, MI=2 -> 64).
// BN=128, BK=64, 256 threads = 8 warps (2m x 4n), mma.m16n8k16 + ldmatrix.x4,
// 3-stage cp.async ring, ONE sync/iter. smem rows 144 B (conflict-free).
//
// NPAIRS==2: C0 = relu(A0@W0^T + A1@W1^T + bias), stored bf16   (layer 1)
// SPLITN   : grid.x doubled: first half -> C0(fp32) = A0@W0^T + bias
//            second half -> C1(fp32) = A0@W1^T                  (layer 2)
// ---------------------------------------------------------------------------
#define BN 128
#define BK 64
#define ROWB 144
#define NSTAGE 3

template<int MI> struct GemmCfg {
    static constexpr int BM = 32 * MI;
    static constexpr int STAGE_A = BM * ROWB;
    static constexpr int STAGE_B = BN * ROWB;
    static constexpr int STAGE_AB = STAGE_A + STAGE_B;
    static constexpr int SMEM = NSTAGE * STAGE_AB;
};

template<int MI>
__device__ __forceinline__ void load_tile(char* sA, char* sB,
        const __nv_bfloat16* __restrict__ A, const __nv_bfloat16* __restrict__ W,
        int M, int K, int row0, int col0, int k0, int tid) {
    // A: BM rows x 8 chunks of 16B; per-thread iterations = MI
#pragma unroll
    for (int it = 0; it < MI; it++) {
        int c = tid + it * 256;
        int r = c >> 3, q = c & 7;
        bool okA = (row0 + r) < M;
        int ra = okA ? (row0 + r) : 0;
        uint32_t sa = (uint32_t)__cvta_generic_to_shared(sA + r * ROWB + q * 16);
        cp_async16(sa, A + (size_t)ra * K + k0 + q * 8, okA);
    }
    // B: 128 rows x 8 chunks = 1024 ops = 4/thread
#pragma unroll
    for (int it = 0; it < 4; it++) {
        int c = tid + it * 256;
        int r = c >> 3, q = c & 7;
        uint32_t sb = (uint32_t)__cvta_generic_to_shared(sB + r * ROWB + q * 16);
        cp_async16(sb, W + (size_t)(col0 + r) * K + k0 + q * 8, true);
    }
    cp_commit();
}

template<int MI, int NPAIRS, bool SPLITN, bool RELU, bool CBF16>
__global__ __launch_bounds__(256, 2)
void gemm_bf16_kernel(const __nv_bfloat16* __restrict__ A0, const __nv_bfloat16* __restrict__ W0,
                      const __nv_bfloat16* __restrict__ A1, const __nv_bfloat16* __restrict__ W1,
                      void* __restrict__ C0v, void* __restrict__ C1v,
                      const float* __restrict__ bias,
                      int M, int N, int K) {
    using Cfg = GemmCfg<MI>;
    extern __shared__ __align__(16) char smem[];

    const int tid = threadIdx.x;
    const int bx = blockIdx.x, by = blockIdx.y;

    const __nv_bfloat16* A = A0;
    const __nv_bfloat16* W = W0;
    void* Cv = C0v;
    bool useBias = (bias != nullptr);
    int col0;
    if (SPLITN) {
        int nHalf = N / BN;
        bool sel = bx >= nHalf;
        col0 = (sel ? bx - nHalf : bx) * BN;
        if (sel) { W = W1; Cv = C1v; useBias = false; }
    } else {
        col0 = bx * BN;
    }
    const int row0 = by * Cfg::BM;

    const int w  = tid >> 5, lane = tid & 31;
    const int wr = w >> 2;          // 0..1 -> m offset wr*(16*MI)
    const int wc = w & 3;           // 0..3 -> n offset wc*32
    const int g  = lane >> 2;       // 0..7
    const int tg = lane & 3;        // 0..3

    const uint32_t aLane = (uint32_t)((lane & 15) * ROWB + (lane >> 4) * 16);
    const uint32_t bLane = (uint32_t)((((lane >> 4) * 8) + (lane & 7)) * ROWB + ((lane >> 3) & 1) * 16);
    const uint32_t sBase = (uint32_t)__cvta_generic_to_shared(smem);

    float acc[MI][4][4];
#pragma unroll
    for (int mi = 0; mi < MI; mi++)
#pragma unroll
        for (int ni = 0; ni < 4; ni++)
#pragma unroll
            for (int q = 0; q < 4; q++) acc[mi][ni][q] = 0.f;

    const int stepsPerK = K / BK;
    const int nT = stepsPerK * NPAIRS;

    auto src_of = [&](int s, const __nv_bfloat16*& Ap, const __nv_bfloat16*& Wp, int& k0) {
        if (NPAIRS == 2 && s >= stepsPerK) { Ap = A1; Wp = W1; k0 = (s - stepsPerK) * BK; }
        else { Ap = A; Wp = W; k0 = s * BK; }
    };

    // prologue: issue loads for tiles 0 .. NSTAGE-2
#pragma unroll
    for (int s = 0; s < NSTAGE - 1; s++) {
        const __nv_bfloat16 *Ap, *Wp; int k0;
        src_of(s, Ap, Wp, k0);
        load_tile<MI>(smem + s * Cfg::STAGE_AB, smem + s * Cfg::STAGE_AB + Cfg::STAGE_A,
                      Ap, Wp, M, K, row0, col0, k0, tid);
    }

    for (int t = 0; t < nT; t++) {
        const int buf = t % NSTAGE;
        if (t + 1 < nT) cp_wait<1>(); else cp_wait<0>();
        __syncthreads();
        if (t + NSTAGE - 1 < nT) {
            const __nv_bfloat16 *Ap, *Wp; int k0;
            src_of(t + NSTAGE - 1, Ap, Wp, k0);
            int nb = (t + NSTAGE - 1) % NSTAGE;
            load_tile<MI>(smem + nb * Cfg::STAGE_AB, smem + nb * Cfg::STAGE_AB + Cfg::STAGE_A,
                          Ap, Wp, M, K, row0, col0, k0, tid);
        }

        const uint32_t aBase = sBase + buf * Cfg::STAGE_AB;
        const uint32_t bBase = aBase + Cfg::STAGE_A;
#pragma unroll
        for (int half = 0; half < 4; half++) {
            const uint32_t ks2 = half * 32;
            uint32_t a[MI][4], b[2][4];
#pragma unroll
            for (int mi = 0; mi < MI; mi++)
                ldsm_x4(a[mi], aBase + (uint32_t)((wr * (16 * MI) + mi * 16) * ROWB) + aLane + ks2);
#pragma unroll
            for (int n2 = 0; n2 < 2; n2++)
                ldsm_x4(b[n2], bBase + (uint32_t)((wc * 32 + n2 * 16) * ROWB) + bLane + ks2);
#pragma unroll
            for (int mi = 0; mi < MI; mi++)
#pragma unroll
                for (int ni = 0; ni < 4; ni++)
                    mma_bf16(acc[mi][ni], a[mi][0], a[mi][1], a[mi][2], a[mi][3],
                             b[ni >> 1][(ni & 1) * 2], b[ni >> 1][(ni & 1) * 2 + 1]);
        }
    }

    // epilogue
#pragma unroll
    for (int mi = 0; mi < MI; mi++) {
        int rbase = row0 + wr * (16 * MI) + mi * 16 + g;
#pragma unroll
        for (int half = 0; half < 2; half++) {
            int r = rbase + half * 8;
            if (r < M) {
#pragma unroll
                for (int ni = 0; ni < 4; ni++) {
                    int c = col0 + wc * 32 + ni * 8 + 2 * tg;
                    float v0 = acc[mi][ni][half * 2 + 0];
                    float v1 = acc[mi][ni][half * 2 + 1];
                    if (useBias) { v0 += bias[c]; v1 += bias[c + 1]; }
                    if (RELU) { v0 = fmaxf(v0, 0.f); v1 = fmaxf(v1, 0.f); }
                    if (CBF16) {
                        __nv_bfloat16* crow = (__nv_bfloat16*)Cv + (size_t)r * N;
                        *(__nv_bfloat162*)(crow + c) = __floats2bfloat162_rn(v0, v1);
                    } else {
                        float* crow = (float*)Cv + (size_t)r * N;
                        *(float2*)(crow + c) = make_float2(v0, v1);
                    }
                }
            }
        }
    }
}

// ---------------------------------------------------------------------------
// Single-block CSR builder: deg count -> scan -> fill, all in one kernel.
// smem deg array is rewritten in-place to running fill cursors after the scan.
// ---------------------------------------------------------------------------
__global__ __launch_bounds__(1024)
void csr_build_kernel(const int* __restrict__ src, const int* __restrict__ dst,
                      int* __restrict__ rowptr, int* __restrict__ csrc) {
    __shared__ int sdeg[N_NODES];   // 40 KB
    __shared__ int part[1024];
    const int t = threadIdx.x;

    for (int i = t; i < N_NODES; i += 1024) sdeg[i] = 0;
    __syncthreads();
    for (int e = t; e < N_EDGES; e += 1024) atomicAdd(&sdeg[dst[e]], 1);
    __syncthreads();

    // exclusive scan over sdeg (CH=10 covers 10240 >= N_NODES)
    const int CH = 10;
    int base = t * CH;
    int local[CH];
    int s = 0;
#pragma unroll
    for (int i = 0; i < CH; i++) {
        int idx = base + i;
        int d = (idx < N_NODES) ? sdeg[idx] : 0;
        local[i] = s;
        s += d;
    }
    part[t] = s;
    __syncthreads();
    for (int off = 1; off < 1024; off <<= 1) {
        int v = part[t];
        int u = (t >= off) ? part[t - off] : 0;
        __syncthreads();
        part[t] = v + u;
        __syncthreads();
    }
    int pre = (t == 0) ? 0 : part[t - 1];
#pragma unroll
    for (int i = 0; i < CH; i++) {
        int idx = base + i;
        if (idx < N_NODES) {
            int start = pre + local[i];
            rowptr[idx] = start;
            sdeg[idx] = start;          // in-place: becomes the fill cursor
        }
    }
    if (t == 1023) rowptr[N_NODES] = part[1023];
    __syncthreads();

    for (int e = t; e < N_EDGES; e += 1024) {
        int slot = atomicAdd(&sdeg[dst[e]], 1);
        csrc[slot] = src[e];
    }
}

// ---------------------------------------------------------------------------
// Fused prep: blocks [0, CVT_BLOCKS) convert fp32->bf16 (x + 4 weights);
// blocks [CVT_BLOCKS, +N_NODES) do layer-1 gather-mean directly from fp32 x.
// ---------------------------------------------------------------------------
#define CVT_N_X   ((size_t)N_NODES * IN_DIM / 4)
#define CVT_N_W1  ((size_t)HID * IN_DIM / 4)
#define CVT_N_W2  ((size_t)OUT_DIM * HID / 4)
#define CVT_TOTAL (CVT_N_X + 2 * CVT_N_W1 + 2 * CVT_N_W2)
#define CVT_BLOCKS 2048

__global__ void prep_kernel(const float* __restrict__ x,   __nv_bfloat16* __restrict__ xb,
                            const float* __restrict__ w1l, __nv_bfloat16* __restrict__ w1lb,
                            const float* __restrict__ w1r, __nv_bfloat16* __restrict__ w1rb,
                            const float* __restrict__ w2l, __nv_bfloat16* __restrict__ w2lb,
                            const float* __restrict__ w2r, __nv_bfloat16* __restrict__ w2rb,
                            const int* __restrict__ rowptr, const int* __restrict__ csrc,
                            __nv_bfloat16* __restrict__ aggb) {
    if (blockIdx.x < CVT_BLOCKS) {
        size_t i = (size_t)blockIdx.x * blockDim.x + threadIdx.x;
        size_t stride = (size_t)CVT_BLOCKS * blockDim.x;
        for (; i < CVT_TOTAL; i += stride) {
            const float* s; __nv_bfloat16* d; size_t off = i;
            if (off < CVT_N_X) { s = x; d = xb; }
            else if ((off -= CVT_N_X) < CVT_N_W1) { s = w1l; d = w1lb; }
            else if ((off -= CVT_N_W1) < CVT_N_W1) { s = w1r; d = w1rb; }
            else if ((off -= CVT_N_W1) < CVT_N_W2) { s = w2l; d = w2lb; }
            else { off -= CVT_N_W2; s = w2r; d = w2rb; }
            float4 v = ((const float4*)s)[off];
            __nv_bfloat162* d2 = (__nv_bfloat162*)d + 2 * off;
            d2[0] = __floats2bfloat162_rn(v.x, v.y);
            d2[1] = __floats2bfloat162_rn(v.z, v.w);
        }
    } else {
        const int n = blockIdx.x - CVT_BLOCKS;
        const int t = threadIdx.x;
        const int beg = rowptr[n], end = rowptr[n + 1];
        float a0 = 0.f, a1 = 0.f, a2 = 0.f, a3 = 0.f;
        int j = beg;
        for (; j + 1 < end; j += 2) {
            int s0 = csrc[j], s1 = csrc[j + 1];
            float4 u0 = *(const float4*)(x + (size_t)s0 * IN_DIM + t * 4);
            float4 u1 = *(const float4*)(x + (size_t)s1 * IN_DIM + t * 4);
            a0 += u0.x + u1.x; a1 += u0.y + u1.y;
            a2 += u0.z + u1.z; a3 += u0.w + u1.w;
        }
        if (j < end) {
            float4 u0 = *(const float4*)(x + (size_t)csrc[j] * IN_DIM + t * 4);
            a0 += u0.x; a1 += u0.y; a2 += u0.z; a3 += u0.w;
        }
        float inv = 1.0f / fmaxf((float)(end - beg), 1.0f);
        __nv_bfloat162* o = (__nv_bfloat162*)(aggb + (size_t)n * IN_DIM + t * 4);
        o[0] = __floats2bfloat162_rn(a0 * inv, a1 * inv);
        o[1] = __floats2bfloat162_rn(a2 * inv, a3 * inv);
    }
}

// ---------------------------------------------------------------------------
// Final fused: gather-mean of t2 + add + log_softmax (shuffle reductions)
// ---------------------------------------------------------------------------
__global__ void final_kernel(float* __restrict__ out,
                             const float* __restrict__ t2,
                             const int* __restrict__ rowptr,
                             const int* __restrict__ csrc) {
    __shared__ float red[8];
    const int n = blockIdx.x;
    const int t = threadIdx.x;
    const int lane = t & 31, wq = t >> 5;
    const int beg = rowptr[n], end = rowptr[n + 1];

    float acc = 0.f;
    int j = beg;
    for (; j + 1 < end; j += 2) {
        int s0 = csrc[j], s1 = csrc[j + 1];
        acc += t2[(size_t)s0 * OUT_DIM + t] + t2[(size_t)s1 * OUT_DIM + t];
    }
    if (j < end) acc += t2[(size_t)csrc[j] * OUT_DIM + t];

    float inv = 1.0f / fmaxf((float)(end - beg), 1.0f);
    size_t idx = (size_t)n * OUT_DIM + t;
    float v = out[idx] + acc * inv;

    float m = v;
#pragma unroll
    for (int s = 16; s > 0; s >>= 1) m = fmaxf(m, __shfl_xor_sync(0xffffffffu, m, s));
    if (lane == 0) red[wq] = m;
    __syncthreads();
    m = red[lane & 7];
#pragma unroll
    for (int s = 4; s > 0; s >>= 1) m = fmaxf(m, __shfl_xor_sync(0xffffffffu, m, s));
    m = __shfl_sync(0xffffffffu, m, 0);

    float e = expf(v - m);
    float sum = e;
#pragma unroll
    for (int s = 16; s > 0; s >>= 1) sum += __shfl_xor_sync(0xffffffffu, sum, s);
    __syncthreads();
    if (lane == 0) red[wq] = sum;
    __syncthreads();
    sum = red[lane & 7];
#pragma unroll
    for (int s = 4; s > 0; s >>= 1) sum += __shfl_xor_sync(0xffffffffu, sum, s);
    sum = __shfl_sync(0xffffffffu, sum, 0);

    out[idx] = v - m - logf(sum);
}

// ---------------------------------------------------------------------------
// Launch
// ---------------------------------------------------------------------------
extern "C" void kernel_launch(void* const* d_in, const int* in_sizes, int n_in,
                              void* d_out, int out_size) {
    const float* x   = (const float*)d_in[0];
    const int*   ei  = (const int*)  d_in[1];
    const float* W1l = (const float*)d_in[2];
    const float* b1l = (const float*)d_in[3];
    const float* W1r = (const float*)d_in[4];
    const float* W2l = (const float*)d_in[5];
    const float* b2l = (const float*)d_in[6];
    const float* W2r = (const float*)d_in[7];
    float* out = (float*)d_out;

    const int* src = ei;
    const int* dst = ei + N_EDGES;

    float* t2;
    __nv_bfloat16 *agg1b, *xb, *h, *w1lb, *w1rb, *w2lb, *w2rb;
    int *rowptr, *csrc;
    cudaGetSymbolAddress((void**)&agg1b, g_agg1b);
    cudaGetSymbolAddress((void**)&xb,    g_xb);
    cudaGetSymbolAddress((void**)&h,     g_h);
    cudaGetSymbolAddress((void**)&t2,    g_t2);
    cudaGetSymbolAddress((void**)&w1lb,  g_w1lb);
    cudaGetSymbolAddress((void**)&w1rb,  g_w1rb);
    cudaGetSymbolAddress((void**)&w2lb,  g_w2lb);
    cudaGetSymbolAddress((void**)&w2rb,  g_w2rb);
    cudaGetSymbolAddress((void**)&rowptr, g_rowptr);
    cudaGetSymbolAddress((void**)&csrc,   g_csrc);

    cudaFuncSetAttribute(gemm_bf16_kernel<4, 2, false, true, true>,
                         cudaFuncAttributeMaxDynamicSharedMemorySize, GemmCfg<4>::SMEM);
    cudaFuncSetAttribute(gemm_bf16_kernel<2, 1, true, false, false>,
                         cudaFuncAttributeMaxDynamicSharedMemorySize, GemmCfg<2>::SMEM);

    // ---- CSR build (single block, single launch) ----
    csr_build_kernel<<<1, 1024>>>(src, dst, rowptr, csrc);

    // ---- fused prep: converts + layer-1 gather-mean (from fp32 x) ----
    prep_kernel<<<CVT_BLOCKS + N_NODES, 256>>>(
        x, xb, W1l, w1lb, W1r, w1rb, W2l, w2lb, W2r, w2rb, rowptr, csrc, agg1b);

    // ---- layer 1: h(bf16) = relu(mean1@W1l^T + x@W1r^T + b1)  [BM=128] ----
    {
        dim3 grid(HID / BN, (N_NODES + GemmCfg<4>::BM - 1) / GemmCfg<4>::BM);
        gemm_bf16_kernel<4, 2, false, true, true><<<grid, 256, GemmCfg<4>::SMEM>>>(
            agg1b, w1lb, xb, w1rb, h, nullptr, b1l, N_NODES, HID, IN_DIM);
    }

    // ---- layer 2: out = h@W2r^T + b2 ; t2 = h@W2l^T (split-N)  [BM=64] ----
    {
        dim3 grid(2 * OUT_DIM / BN, (N_NODES + GemmCfg<2>::BM - 1) / GemmCfg<2>::BM);
        gemm_bf16_kernel<2, 1, true, false, false><<<grid, 256, GemmCfg<2>::SMEM>>>(
            h, w2rb, nullptr, w2lb, out, t2, b2l, N_NODES, OUT_DIM, HID);
    }

    // ---- fused: out = log_softmax(out + mean_gather(t2)) ----
    final_kernel<<<N_NODES, 256>>>(out, t2, rowptr, csrc);
}

// round 14
// speedup vs baseline: 1.0051x; 1.0051x over previous
#include <cuda_runtime.h>
#include <cuda_bf16.h>
#include <math.h>
#include <stdint.h>

#define N_NODES 10000
#define N_EDGES 80000
#define IN_DIM  1024
#define HID     4096
#define OUT_DIM 256

// ---------------------------------------------------------------------------
// Scratch (device globals)
// ---------------------------------------------------------------------------
__device__ __align__(16) __nv_bfloat16 g_agg1b[(size_t)N_NODES * IN_DIM];   // 20 MB
__device__ __align__(16) __nv_bfloat16 g_xb[(size_t)N_NODES * IN_DIM];      // 20 MB
__device__ __align__(16) __nv_bfloat16 g_h[(size_t)N_NODES * HID];          // 80 MB
__device__ __align__(16) float g_t2[(size_t)N_NODES * OUT_DIM];             // 10 MB
__device__ __align__(16) __nv_bfloat16 g_w1lb[(size_t)HID * IN_DIM];        // 8 MB
__device__ __align__(16) __nv_bfloat16 g_w1rb[(size_t)HID * IN_DIM];        // 8 MB
__device__ __align__(16) __nv_bfloat16 g_w2lb[(size_t)OUT_DIM * HID];       // 2 MB
__device__ __align__(16) __nv_bfloat16 g_w2rb[(size_t)OUT_DIM * HID];       // 2 MB
// CSR
__device__ int g_rowptr[N_NODES + 1];
__device__ int g_csrc[N_EDGES];

// ---------------------------------------------------------------------------
// MMA / async-copy helpers
// ---------------------------------------------------------------------------
__device__ __forceinline__ void mma_bf16(float c[4],
        uint32_t a0, uint32_t a1, uint32_t a2, uint32_t a3,
        uint32_t b0, uint32_t b1) {
    asm volatile(
        "mma.sync.aligned.m16n8k16.row.col.f32.bf16.bf16.f32 "
        "{%0,%1,%2,%3},{%4,%5,%6,%7},{%8,%9},{%0,%1,%2,%3};"
        : "+f"(c[0]), "+f"(c[1]), "+f"(c[2]), "+f"(c[3])
        : "r"(a0), "r"(a1), "r"(a2), "r"(a3), "r"(b0), "r"(b1));
}
__device__ __forceinline__ void ldsm_x4(uint32_t r[4], uint32_t addr) {
    asm volatile("ldmatrix.sync.aligned.m8n8.x4.shared.b16 {%0,%1,%2,%3}, [%4];"
                 : "=r"(r[0]), "=r"(r[1]), "=r"(r[2]), "=r"(r[3]) : "r"(addr));
}
__device__ __forceinline__ void cp_async16(uint32_t smem, const void* g, bool valid) {
    int sz = valid ? 16 : 0;
    asm volatile("cp.async.cg.shared.global [%0], [%1], 16, %2;\n"
                 :: "r"(smem), "l"(g), "r"(sz));
}
__device__ __forceinline__ void cp_commit() { asm volatile("cp.async.commit_group;\n"); }
template<int W> __device__ __forceinline__ void cp_wait() {
    asm volatile("cp.async.wait_group %0;\n" :: "n"(W));
}

// ---------------------------------------------------------------------------
// BF16 tensor-core GEMM:  C[M,N] = A[M,K] @ W[N,K]^T   (A,W bf16; C fp32/bf16)
// BM=BN=128, BK=64, 256 threads = 8 warps (2m x 4n), warp tile 64x32,
// mma.sync.m16n8k16 + ldmatrix.x4, 3-stage cp.async ring, ONE sync/iter.
// smem rows 144 B (128 data + 16 pad): conflict-free ldmatrix (144%128=16).
//
// NPAIRS==2: C0 = relu(A0@W0^T + A1@W1^T + bias), stored bf16   (layer 1)
// SPLITN   : grid.x doubled: first half -> C0(fp32) = A0@W0^T + bias
//            second half -> C1(fp32) = A0@W1^T                  (layer 2)
// ---------------------------------------------------------------------------
#define BM 128
#define BN 128
#define BK 64
#define ROWB 144
#define STAGE_A (BM * ROWB)            // 18432
#define STAGE_AB (2 * STAGE_A)         // 36864 (A then B)
#define NSTAGE 3
#define SMEM_BYTES (NSTAGE * STAGE_AB) // 110592

__device__ __forceinline__ void load_tile(char* sA, char* sB,
        const __nv_bfloat16* __restrict__ A, const __nv_bfloat16* __restrict__ W,
        int M, int K, int row0, int col0, int k0, int tid) {
#pragma unroll
    for (int it = 0; it < 4; it++) {
        int c = tid + it * 256;
        int r = c >> 3, q = c & 7;
        bool okA = (row0 + r) < M;
        int ra = okA ? (row0 + r) : 0;
        uint32_t sa = (uint32_t)__cvta_generic_to_shared(sA + r * ROWB + q * 16);
        cp_async16(sa, A + (size_t)ra * K + k0 + q * 8, okA);
        uint32_t sb = (uint32_t)__cvta_generic_to_shared(sB + r * ROWB + q * 16);
        cp_async16(sb, W + (size_t)(col0 + r) * K + k0 + q * 8, true);
    }
    cp_commit();
}

template<int NPAIRS, bool SPLITN, bool RELU, bool CBF16>
__global__ __launch_bounds__(256, 2)
void gemm_bf16_kernel(const __nv_bfloat16* __restrict__ A0, const __nv_bfloat16* __restrict__ W0,
                      const __nv_bfloat16* __restrict__ A1, const __nv_bfloat16* __restrict__ W1,
                      void* __restrict__ C0v, void* __restrict__ C1v,
                      const float* __restrict__ bias,
                      int M, int N, int K) {
    extern __shared__ __align__(16) char smem[];

    const int tid = threadIdx.x;
    const int bx = blockIdx.x, by = blockIdx.y;

    const __nv_bfloat16* A = A0;
    const __nv_bfloat16* W = W0;
    void* Cv = C0v;
    bool useBias = (bias != nullptr);
    int col0;
    if (SPLITN) {
        int nHalf = N / BN;
        bool sel = bx >= nHalf;
        col0 = (sel ? bx - nHalf : bx) * BN;
        if (sel) { W = W1; Cv = C1v; useBias = false; }
    } else {
        col0 = bx * BN;
    }
    const int row0 = by * BM;

    const int w  = tid >> 5, lane = tid & 31;
    const int wr = w >> 2;          // 0..1 -> m offset wr*64
    const int wc = w & 3;           // 0..3 -> n offset wc*32
    const int g  = lane >> 2;       // 0..7
    const int tg = lane & 3;        // 0..3

    const uint32_t aLane = (uint32_t)((lane & 15) * ROWB + (lane >> 4) * 16);
    const uint32_t bLane = (uint32_t)((((lane >> 4) * 8) + (lane & 7)) * ROWB + ((lane >> 3) & 1) * 16);
    const uint32_t sBase = (uint32_t)__cvta_generic_to_shared(smem);

    float acc[4][4][4];
#pragma unroll
    for (int mi = 0; mi < 4; mi++)
#pragma unroll
        for (int ni = 0; ni < 4; ni++)
#pragma unroll
            for (int q = 0; q < 4; q++) acc[mi][ni][q] = 0.f;

    const int stepsPerK = K / BK;
    const int nT = stepsPerK * NPAIRS;

    auto src_of = [&](int s, const __nv_bfloat16*& Ap, const __nv_bfloat16*& Wp, int& k0) {
        if (NPAIRS == 2 && s >= stepsPerK) { Ap = A1; Wp = W1; k0 = (s - stepsPerK) * BK; }
        else { Ap = A; Wp = W; k0 = s * BK; }
    };

    // prologue: issue loads for tiles 0 .. NSTAGE-2
#pragma unroll
    for (int s = 0; s < NSTAGE - 1; s++) {
        const __nv_bfloat16 *Ap, *Wp; int k0;
        src_of(s, Ap, Wp, k0);
        load_tile(smem + s * STAGE_AB, smem + s * STAGE_AB + STAGE_A,
                  Ap, Wp, M, K, row0, col0, k0, tid);
    }

    for (int t = 0; t < nT; t++) {
        const int buf = t % NSTAGE;
        if (t + 1 < nT) cp_wait<1>(); else cp_wait<0>();
        __syncthreads();
        if (t + NSTAGE - 1 < nT) {
            const __nv_bfloat16 *Ap, *Wp; int k0;
            src_of(t + NSTAGE - 1, Ap, Wp, k0);
            int nb = (t + NSTAGE - 1) % NSTAGE;
            load_tile(smem + nb * STAGE_AB, smem + nb * STAGE_AB + STAGE_A,
                      Ap, Wp, M, K, row0, col0, k0, tid);
        }

        const uint32_t aBase = sBase + buf * STAGE_AB;
        const uint32_t bBase = aBase + STAGE_A;
#pragma unroll
        for (int half = 0; half < 4; half++) {
            const uint32_t ks2 = half * 32;
            uint32_t a[4][4], b[2][4];
#pragma unroll
            for (int mi = 0; mi < 4; mi++)
                ldsm_x4(a[mi], aBase + (uint32_t)((wr * 64 + mi * 16) * ROWB) + aLane + ks2);
#pragma unroll
            for (int n2 = 0; n2 < 2; n2++)
                ldsm_x4(b[n2], bBase + (uint32_t)((wc * 32 + n2 * 16) * ROWB) + bLane + ks2);
#pragma unroll
            for (int mi = 0; mi < 4; mi++)
#pragma unroll
                for (int ni = 0; ni < 4; ni++)
                    mma_bf16(acc[mi][ni], a[mi][0], a[mi][1], a[mi][2], a[mi][3],
                             b[ni >> 1][(ni & 1) * 2], b[ni >> 1][(ni & 1) * 2 + 1]);
        }
    }

    // epilogue
#pragma unroll
    for (int mi = 0; mi < 4; mi++) {
        int rbase = row0 + wr * 64 + mi * 16 + g;
#pragma unroll
        for (int half = 0; half < 2; half++) {
            int r = rbase + half * 8;
            if (r < M) {
#pragma unroll
                for (int ni = 0; ni < 4; ni++) {
                    int c = col0 + wc * 32 + ni * 8 + 2 * tg;
                    float v0 = acc[mi][ni][half * 2 + 0];
                    float v1 = acc[mi][ni][half * 2 + 1];
                    if (useBias) { v0 += bias[c]; v1 += bias[c + 1]; }
                    if (RELU) { v0 = fmaxf(v0, 0.f); v1 = fmaxf(v1, 0.f); }
                    if (CBF16) {
                        __nv_bfloat16* crow = (__nv_bfloat16*)Cv + (size_t)r * N;
                        *(__nv_bfloat162*)(crow + c) = __floats2bfloat162_rn(v0, v1);
                    } else {
                        float* crow = (float*)Cv + (size_t)r * N;
                        *(float2*)(crow + c) = make_float2(v0, v1);
                    }
                }
            }
        }
    }
}

// ---------------------------------------------------------------------------
// Single-block CSR builder: deg count -> scan -> fill, all in one kernel.
// smem deg array is rewritten in-place to running fill cursors after the scan.
// ---------------------------------------------------------------------------
__global__ __launch_bounds__(1024)
void csr_build_kernel(const int* __restrict__ src, const int* __restrict__ dst,
                      int* __restrict__ rowptr, int* __restrict__ csrc) {
    __shared__ int sdeg[N_NODES];   // 40 KB
    __shared__ int part[1024];
    const int t = threadIdx.x;

    for (int i = t; i < N_NODES; i += 1024) sdeg[i] = 0;
    __syncthreads();
    for (int e = t; e < N_EDGES; e += 1024) atomicAdd(&sdeg[dst[e]], 1);
    __syncthreads();

    // exclusive scan over sdeg (CH=10 covers 10240 >= N_NODES)
    const int CH = 10;
    int base = t * CH;
    int local[CH];
    int s = 0;
#pragma unroll
    for (int i = 0; i < CH; i++) {
        int idx = base + i;
        int d = (idx < N_NODES) ? sdeg[idx] : 0;
        local[i] = s;
        s += d;
    }
    part[t] = s;
    __syncthreads();
    for (int off = 1; off < 1024; off <<= 1) {
        int v = part[t];
        int u = (t >= off) ? part[t - off] : 0;
        __syncthreads();
        part[t] = v + u;
        __syncthreads();
    }
    int pre = (t == 0) ? 0 : part[t - 1];
#pragma unroll
    for (int i = 0; i < CH; i++) {
        int idx = base + i;
        if (idx < N_NODES) {
            int start = pre + local[i];
            rowptr[idx] = start;
            sdeg[idx] = start;          // in-place: becomes the fill cursor
        }
    }
    if (t == 1023) rowptr[N_NODES] = part[1023];
    __syncthreads();

    for (int e = t; e < N_EDGES; e += 1024) {
        int slot = atomicAdd(&sdeg[dst[e]], 1);
        csrc[slot] = src[e];
    }
}

// ---------------------------------------------------------------------------
// Fused prep: blocks [0, CVT_BLOCKS) convert fp32->bf16 (x + 4 weights);
// blocks [CVT_BLOCKS, +N_NODES) do layer-1 gather-mean directly from fp32 x.
// ---------------------------------------------------------------------------
#define CVT_N_X   ((size_t)N_NODES * IN_DIM / 4)
#define CVT_N_W1  ((size_t)HID * IN_DIM / 4)
#define CVT_N_W2  ((size_t)OUT_DIM * HID / 4)
#define CVT_TOTAL (CVT_N_X + 2 * CVT_N_W1 + 2 * CVT_N_W2)
#define CVT_BLOCKS 2048

__global__ void prep_kernel(const float* __restrict__ x,   __nv_bfloat16* __restrict__ xb,
                            const float* __restrict__ w1l, __nv_bfloat16* __restrict__ w1lb,
                            const float* __restrict__ w1r, __nv_bfloat16* __restrict__ w1rb,
                            const float* __restrict__ w2l, __nv_bfloat16* __restrict__ w2lb,
                            const float* __restrict__ w2r, __nv_bfloat16* __restrict__ w2rb,
                            const int* __restrict__ rowptr, const int* __restrict__ csrc,
                            __nv_bfloat16* __restrict__ aggb) {
    if (blockIdx.x < CVT_BLOCKS) {
        size_t i = (size_t)blockIdx.x * blockDim.x + threadIdx.x;
        size_t stride = (size_t)CVT_BLOCKS * blockDim.x;
        for (; i < CVT_TOTAL; i += stride) {
            const float* s; __nv_bfloat16* d; size_t off = i;
            if (off < CVT_N_X) { s = x; d = xb; }
            else if ((off -= CVT_N_X) < CVT_N_W1) { s = w1l; d = w1lb; }
            else if ((off -= CVT_N_W1) < CVT_N_W1) { s = w1r; d = w1rb; }
            else if ((off -= CVT_N_W1) < CVT_N_W2) { s = w2l; d = w2lb; }
            else { off -= CVT_N_W2; s = w2r; d = w2rb; }
            float4 v = ((const float4*)s)[off];
            __nv_bfloat162* d2 = (__nv_bfloat162*)d + 2 * off;
            d2[0] = __floats2bfloat162_rn(v.x, v.y);
            d2[1] = __floats2bfloat162_rn(v.z, v.w);
        }
    } else {
        const int n = blockIdx.x - CVT_BLOCKS;
        const int t = threadIdx.x;
        const int beg = rowptr[n], end = rowptr[n + 1];
        float a0 = 0.f, a1 = 0.f, a2 = 0.f, a3 = 0.f;
        int j = beg;
        for (; j + 1 < end; j += 2) {
            int s0 = csrc[j], s1 = csrc[j + 1];
            float4 u0 = *(const float4*)(x + (size_t)s0 * IN_DIM + t * 4);
            float4 u1 = *(const float4*)(x + (size_t)s1 * IN_DIM + t * 4);
            a0 += u0.x + u1.x; a1 += u0.y + u1.y;
            a2 += u0.z + u1.z; a3 += u0.w + u1.w;
        }
        if (j < end) {
            float4 u0 = *(const float4*)(x + (size_t)csrc[j] * IN_DIM + t * 4);
            a0 += u0.x; a1 += u0.y; a2 += u0.z; a3 += u0.w;
        }
        float inv = 1.0f / fmaxf((float)(end - beg), 1.0f);
        __nv_bfloat162* o = (__nv_bfloat162*)(aggb + (size_t)n * IN_DIM + t * 4);
        o[0] = __floats2bfloat162_rn(a0 * inv, a1 * inv);
        o[1] = __floats2bfloat162_rn(a2 * inv, a3 * inv);
    }
}

// ---------------------------------------------------------------------------
// Final fused: gather-mean of t2 + add + log_softmax (shuffle reductions)
// ---------------------------------------------------------------------------
__global__ void final_kernel(float* __restrict__ out,
                             const float* __restrict__ t2,
                             const int* __restrict__ rowptr,
                             const int* __restrict__ csrc) {
    __shared__ float red[8];
    const int n = blockIdx.x;
    const int t = threadIdx.x;
    const int lane = t & 31, wq = t >> 5;
    const int beg = rowptr[n], end = rowptr[n + 1];

    float acc = 0.f;
    int j = beg;
    for (; j + 1 < end; j += 2) {
        int s0 = csrc[j], s1 = csrc[j + 1];
        acc += t2[(size_t)s0 * OUT_DIM + t] + t2[(size_t)s1 * OUT_DIM + t];
    }
    if (j < end) acc += t2[(size_t)csrc[j] * OUT_DIM + t];

    float inv = 1.0f / fmaxf((float)(end - beg), 1.0f);
    size_t idx = (size_t)n * OUT_DIM + t;
    float v = out[idx] + acc * inv;

    float m = v;
#pragma unroll
    for (int s = 16; s > 0; s >>= 1) m = fmaxf(m, __shfl_xor_sync(0xffffffffu, m, s));
    if (lane == 0) red[wq] = m;
    __syncthreads();
    m = red[lane & 7];
#pragma unroll
    for (int s = 4; s > 0; s >>= 1) m = fmaxf(m, __shfl_xor_sync(0xffffffffu, m, s));
    m = __shfl_sync(0xffffffffu, m, 0);

    float e = expf(v - m);
    float sum = e;
#pragma unroll
    for (int s = 16; s > 0; s >>= 1) sum += __shfl_xor_sync(0xffffffffu, sum, s);
    __syncthreads();
    if (lane == 0) red[wq] = sum;
    __syncthreads();
    sum = red[lane & 7];
#pragma unroll
    for (int s = 4; s > 0; s >>= 1) sum += __shfl_xor_sync(0xffffffffu, sum, s);
    sum = __shfl_sync(0xffffffffu, sum, 0);

    out[idx] = v - m - logf(sum);
}

// ---------------------------------------------------------------------------
// Launch
// ---------------------------------------------------------------------------
extern "C" void kernel_launch(void* const* d_in, const int* in_sizes, int n_in,
                              void* d_out, int out_size) {
    const float* x   = (const float*)d_in[0];
    const int*   ei  = (const int*)  d_in[1];
    const float* W1l = (const float*)d_in[2];
    const float* b1l = (const float*)d_in[3];
    const float* W1r = (const float*)d_in[4];
    const float* W2l = (const float*)d_in[5];
    const float* b2l = (const float*)d_in[6];
    const float* W2r = (const float*)d_in[7];
    float* out = (float*)d_out;

    const int* src = ei;
    const int* dst = ei + N_EDGES;

    float* t2;
    __nv_bfloat16 *agg1b, *xb, *h, *w1lb, *w1rb, *w2lb, *w2rb;
    int *rowptr, *csrc;
    cudaGetSymbolAddress((void**)&agg1b, g_agg1b);
    cudaGetSymbolAddress((void**)&xb,    g_xb);
    cudaGetSymbolAddress((void**)&h,     g_h);
    cudaGetSymbolAddress((void**)&t2,    g_t2);
    cudaGetSymbolAddress((void**)&w1lb,  g_w1lb);
    cudaGetSymbolAddress((void**)&w1rb,  g_w1rb);
    cudaGetSymbolAddress((void**)&w2lb,  g_w2lb);
    cudaGetSymbolAddress((void**)&w2rb,  g_w2rb);
    cudaGetSymbolAddress((void**)&rowptr, g_rowptr);
    cudaGetSymbolAddress((void**)&csrc,   g_csrc);

    cudaFuncSetAttribute(gemm_bf16_kernel<2, false, true, true>,
                         cudaFuncAttributeMaxDynamicSharedMemorySize, SMEM_BYTES);
    cudaFuncSetAttribute(gemm_bf16_kernel<1, true, false, false>,
                         cudaFuncAttributeMaxDynamicSharedMemorySize, SMEM_BYTES);

    // ---- CSR build (single block, single launch) ----
    csr_build_kernel<<<1, 1024>>>(src, dst, rowptr, csrc);

    // ---- fused prep: converts + layer-1 gather-mean (from fp32 x) ----
    prep_kernel<<<CVT_BLOCKS + N_NODES, 256>>>(
        x, xb, W1l, w1lb, W1r, w1rb, W2l, w2lb, W2r, w2rb, rowptr, csrc, agg1b);

    // ---- layer 1: h(bf16) = relu(mean1@W1l^T + x@W1r^T + b1)  [BM=128] ----
    {
        dim3 grid(HID / BN, (N_NODES + BM - 1) / BM);
        gemm_bf16_kernel<2, false, true, true><<<grid, 256, SMEM_BYTES>>>(
            agg1b, w1lb, xb, w1rb, h, nullptr, b1l, N_NODES, HID, IN_DIM);
    }

    // ---- layer 2: out = h@W2r^T + b2 ; t2 = h@W2l^T (split-N)  [BM=128] ----
    {
        dim3 grid(2 * OUT_DIM / BN, (N_NODES + BM - 1) / BM);
        gemm_bf16_kernel<1, true, false, false><<<grid, 256, SMEM_BYTES>>>(
            h, w2rb, nullptr, w2lb, out, t2, b2l, N_NODES, OUT_DIM, HID);
    }

    // ---- fused: out = log_softmax(out + mean_gather(t2)) ----
    final_kernel<<<N_NODES, 256>>>(out, t2, rowptr, csrc);
}

// round 15
// speedup vs baseline: 1.0961x; 1.0905x over previous
#include <cuda_runtime.h>
#include <cuda_bf16.h>
#include <math.h>
#include <stdint.h>

#define N_NODES 10000
#define N_EDGES 80000
#define IN_DIM  1024
#define HID     4096
#define OUT_DIM 256

// ---------------------------------------------------------------------------
// Scratch (device globals)
// ---------------------------------------------------------------------------
__device__ __align__(16) __nv_bfloat16 g_agg1b[(size_t)N_NODES * IN_DIM];   // 20 MB
__device__ __align__(16) __nv_bfloat16 g_xb[(size_t)N_NODES * IN_DIM];      // 20 MB
__device__ __align__(16) __nv_bfloat16 g_h[(size_t)N_NODES * HID];          // 80 MB
__device__ __align__(16) float g_t2[(size_t)N_NODES * OUT_DIM];             // 10 MB
__device__ __align__(16) __nv_bfloat16 g_w1lb[(size_t)HID * IN_DIM];        // 8 MB
__device__ __align__(16) __nv_bfloat16 g_w1rb[(size_t)HID * IN_DIM];        // 8 MB
__device__ __align__(16) __nv_bfloat16 g_w2lb[(size_t)OUT_DIM * HID];       // 2 MB
__device__ __align__(16) __nv_bfloat16 g_w2rb[(size_t)OUT_DIM * HID];       // 2 MB
// CSR
__device__ int g_deg[N_NODES];
__device__ int g_rowptr[N_NODES + 1];
__device__ int g_pos[N_NODES];
__device__ int g_csrc[N_EDGES];

// ---------------------------------------------------------------------------
// MMA / async-copy helpers
// ---------------------------------------------------------------------------
__device__ __forceinline__ void mma_bf16(float c[4],
        uint32_t a0, uint32_t a1, uint32_t a2, uint32_t a3,
        uint32_t b0, uint32_t b1) {
    asm volatile(
        "mma.sync.aligned.m16n8k16.row.col.f32.bf16.bf16.f32 "
        "{%0,%1,%2,%3},{%4,%5,%6,%7},{%8,%9},{%0,%1,%2,%3};"
        : "+f"(c[0]), "+f"(c[1]), "+f"(c[2]), "+f"(c[3])
        : "r"(a0), "r"(a1), "r"(a2), "r"(a3), "r"(b0), "r"(b1));
}
__device__ __forceinline__ void ldsm_x4(uint32_t r[4], uint32_t addr) {
    asm volatile("ldmatrix.sync.aligned.m8n8.x4.shared.b16 {%0,%1,%2,%3}, [%4];"
                 : "=r"(r[0]), "=r"(r[1]), "=r"(r[2]), "=r"(r[3]) : "r"(addr));
}
__device__ __forceinline__ void cp_async16(uint32_t smem, const void* g, bool valid) {
    int sz = valid ? 16 : 0;
    asm volatile("cp.async.cg.shared.global [%0], [%1], 16, %2;\n"
                 :: "r"(smem), "l"(g), "r"(sz));
}
__device__ __forceinline__ void cp_commit() { asm volatile("cp.async.commit_group;\n"); }
template<int W> __device__ __forceinline__ void cp_wait() {
    asm volatile("cp.async.wait_group %0;\n" :: "n"(W));
}

// ---------------------------------------------------------------------------
// BF16 tensor-core GEMM:  C[M,N] = A[M,K] @ W[N,K]^T   (A,W bf16; C fp32/bf16)
// BM=BN=128, BK=64, 256 threads = 8 warps (2m x 4n), warp tile 64x32,
// mma.sync.m16n8k16 + ldmatrix.x4, 3-stage cp.async ring, ONE sync/iter.
// smem rows 144 B (128 data + 16 pad): conflict-free ldmatrix (144%128=16).
//
// NPAIRS==2: C0 = relu(A0@W0^T + A1@W1^T + bias), stored bf16   (layer 1)
// SPLITN   : grid.x doubled: first half -> C0(fp32) = A0@W0^T + bias
//            second half -> C1(fp32) = A0@W1^T                  (layer 2)
// SPLITK   : gridDim.z = 2; each z-slice covers K/2; epilogue atomicAdd
//            into pre-zeroed fp32 C; bias added only by z==0.
// ---------------------------------------------------------------------------
#define BM 128
#define BN 128
#define BK 64
#define ROWB 144
#define STAGE_A (BM * ROWB)            // 18432
#define STAGE_AB (2 * STAGE_A)         // 36864 (A then B)
#define NSTAGE 3
#define SMEM_BYTES (NSTAGE * STAGE_AB) // 110592

__device__ __forceinline__ void load_tile(char* sA, char* sB,
        const __nv_bfloat16* __restrict__ A, const __nv_bfloat16* __restrict__ W,
        int M, int K, int row0, int col0, int k0, int tid) {
#pragma unroll
    for (int it = 0; it < 4; it++) {
        int c = tid + it * 256;
        int r = c >> 3, q = c & 7;
        bool okA = (row0 + r) < M;
        int ra = okA ? (row0 + r) : 0;
        uint32_t sa = (uint32_t)__cvta_generic_to_shared(sA + r * ROWB + q * 16);
        cp_async16(sa, A + (size_t)ra * K + k0 + q * 8, okA);
        uint32_t sb = (uint32_t)__cvta_generic_to_shared(sB + r * ROWB + q * 16);
        cp_async16(sb, W + (size_t)(col0 + r) * K + k0 + q * 8, true);
    }
    cp_commit();
}

template<int NPAIRS, bool SPLITN, bool RELU, bool CBF16, bool SPLITK>
__global__ __launch_bounds__(256, 2)
void gemm_bf16_kernel(const __nv_bfloat16* __restrict__ A0, const __nv_bfloat16* __restrict__ W0,
                      const __nv_bfloat16* __restrict__ A1, const __nv_bfloat16* __restrict__ W1,
                      void* __restrict__ C0v, void* __restrict__ C1v,
                      const float* __restrict__ bias,
                      int M, int N, int K) {
    extern __shared__ __align__(16) char smem[];

    const int tid = threadIdx.x;
    const int bx = blockIdx.x, by = blockIdx.y;

    const __nv_bfloat16* A = A0;
    const __nv_bfloat16* W = W0;
    void* Cv = C0v;
    bool useBias = (bias != nullptr);
    int col0;
    if (SPLITN) {
        int nHalf = N / BN;
        bool sel = bx >= nHalf;
        col0 = (sel ? bx - nHalf : bx) * BN;
        if (sel) { W = W1; Cv = C1v; useBias = false; }
    } else {
        col0 = bx * BN;
    }
    const int row0 = by * BM;

    const int Keff = SPLITK ? K / 2 : K;
    const int koff = SPLITK ? blockIdx.z * Keff : 0;
    if (SPLITK && blockIdx.z != 0) useBias = false;

    const int w  = tid >> 5, lane = tid & 31;
    const int wr = w >> 2;          // 0..1 -> m offset wr*64
    const int wc = w & 3;           // 0..3 -> n offset wc*32
    const int g  = lane >> 2;       // 0..7
    const int tg = lane & 3;        // 0..3

    const uint32_t aLane = (uint32_t)((lane & 15) * ROWB + (lane >> 4) * 16);
    const uint32_t bLane = (uint32_t)((((lane >> 4) * 8) + (lane & 7)) * ROWB + ((lane >> 3) & 1) * 16);
    const uint32_t sBase = (uint32_t)__cvta_generic_to_shared(smem);

    float acc[4][4][4];
#pragma unroll
    for (int mi = 0; mi < 4; mi++)
#pragma unroll
        for (int ni = 0; ni < 4; ni++)
#pragma unroll
            for (int q = 0; q < 4; q++) acc[mi][ni][q] = 0.f;

    const int stepsPerK = Keff / BK;
    const int nT = stepsPerK * NPAIRS;

    auto src_of = [&](int s, const __nv_bfloat16*& Ap, const __nv_bfloat16*& Wp, int& k0) {
        if (NPAIRS == 2 && s >= stepsPerK) { Ap = A1; Wp = W1; k0 = koff + (s - stepsPerK) * BK; }
        else { Ap = A; Wp = W; k0 = koff + s * BK; }
    };

    // prologue: issue loads for tiles 0 .. NSTAGE-2
#pragma unroll
    for (int s = 0; s < NSTAGE - 1; s++) {
        const __nv_bfloat16 *Ap, *Wp; int k0;
        src_of(s, Ap, Wp, k0);
        load_tile(smem + s * STAGE_AB, smem + s * STAGE_AB + STAGE_A,
                  Ap, Wp, M, K, row0, col0, k0, tid);
    }

    for (int t = 0; t < nT; t++) {
        const int buf = t % NSTAGE;
        if (t + 1 < nT) cp_wait<1>(); else cp_wait<0>();
        __syncthreads();
        if (t + NSTAGE - 1 < nT) {
            const __nv_bfloat16 *Ap, *Wp; int k0;
            src_of(t + NSTAGE - 1, Ap, Wp, k0);
            int nb = (t + NSTAGE - 1) % NSTAGE;
            load_tile(smem + nb * STAGE_AB, smem + nb * STAGE_AB + STAGE_A,
                      Ap, Wp, M, K, row0, col0, k0, tid);
        }

        const uint32_t aBase = sBase + buf * STAGE_AB;
        const uint32_t bBase = aBase + STAGE_A;
#pragma unroll
        for (int half = 0; half < 4; half++) {
            const uint32_t ks2 = half * 32;
            uint32_t a[4][4], b[2][4];
#pragma unroll
            for (int mi = 0; mi < 4; mi++)
                ldsm_x4(a[mi], aBase + (uint32_t)((wr * 64 + mi * 16) * ROWB) + aLane + ks2);
#pragma unroll
            for (int n2 = 0; n2 < 2; n2++)
                ldsm_x4(b[n2], bBase + (uint32_t)((wc * 32 + n2 * 16) * ROWB) + bLane + ks2);
#pragma unroll
            for (int mi = 0; mi < 4; mi++)
#pragma unroll
                for (int ni = 0; ni < 4; ni++)
                    mma_bf16(acc[mi][ni], a[mi][0], a[mi][1], a[mi][2], a[mi][3],
                             b[ni >> 1][(ni & 1) * 2], b[ni >> 1][(ni & 1) * 2 + 1]);
        }
    }

    // epilogue
#pragma unroll
    for (int mi = 0; mi < 4; mi++) {
        int rbase = row0 + wr * 64 + mi * 16 + g;
#pragma unroll
        for (int half = 0; half < 2; half++) {
            int r = rbase + half * 8;
            if (r < M) {
#pragma unroll
                for (int ni = 0; ni < 4; ni++) {
                    int c = col0 + wc * 32 + ni * 8 + 2 * tg;
                    float v0 = acc[mi][ni][half * 2 + 0];
                    float v1 = acc[mi][ni][half * 2 + 1];
                    if (useBias) { v0 += bias[c]; v1 += bias[c + 1]; }
                    if (RELU) { v0 = fmaxf(v0, 0.f); v1 = fmaxf(v1, 0.f); }
                    if (CBF16) {
                        __nv_bfloat16* crow = (__nv_bfloat16*)Cv + (size_t)r * N;
                        *(__nv_bfloat162*)(crow + c) = __floats2bfloat162_rn(v0, v1);
                    } else if (SPLITK) {
                        float* crow = (float*)Cv + (size_t)r * N;
                        atomicAdd(crow + c, v0);
                        atomicAdd(crow + c + 1, v1);
                    } else {
                        float* crow = (float*)Cv + (size_t)r * N;
                        *(float2*)(crow + c) = make_float2(v0, v1);
                    }
                }
            }
        }
    }
}

// ---------------------------------------------------------------------------
// CSR construction (multi-kernel, as in R12 — measured faster than 1-block)
// ---------------------------------------------------------------------------
__global__ void zero_int_kernel(int* __restrict__ p, int n) {
    int i = blockIdx.x * blockDim.x + threadIdx.x;
    if (i < n) p[i] = 0;
}
__global__ void deg_kernel(const int* __restrict__ dst, int* __restrict__ deg) {
    int e = blockIdx.x * blockDim.x + threadIdx.x;
    if (e < N_EDGES) atomicAdd(&deg[dst[e]], 1);
}
__global__ void scan_kernel(const int* __restrict__ deg, int* __restrict__ rowptr,
                            int* __restrict__ pos) {
    __shared__ int part[1024];
    const int CH = 10;
    int t = threadIdx.x;
    int base = t * CH;
    int local[CH];
    int s = 0;
#pragma unroll
    for (int i = 0; i < CH; i++) {
        int idx = base + i;
        int d = (idx < N_NODES) ? deg[idx] : 0;
        local[i] = s;
        s += d;
    }
    part[t] = s;
    __syncthreads();
    for (int off = 1; off < 1024; off <<= 1) {
        int v = part[t];
        int u = (t >= off) ? part[t - off] : 0;
        __syncthreads();
        part[t] = v + u;
        __syncthreads();
    }
    int pre = (t == 0) ? 0 : part[t - 1];
#pragma unroll
    for (int i = 0; i < CH; i++) {
        int idx = base + i;
        if (idx < N_NODES) { rowptr[idx] = pre + local[i]; pos[idx] = pre + local[i]; }
    }
    if (t == 1023) rowptr[N_NODES] = part[1023];
}
__global__ void fill_csr_kernel(const int* __restrict__ src, const int* __restrict__ dst,
                                int* __restrict__ pos, int* __restrict__ csrc) {
    int e = blockIdx.x * blockDim.x + threadIdx.x;
    if (e < N_EDGES) {
        int slot = atomicAdd(&pos[dst[e]], 1);
        csrc[slot] = src[e];
    }
}

// ---------------------------------------------------------------------------
// Fused prep: blocks [0, CVT_BLOCKS)           : fp32->bf16 converts
//             [CVT_BLOCKS, +ZERO_BLOCKS)       : zero out (d_out) and t2
//             [CVT_BLOCKS+ZERO_BLOCKS, +N_NODES): layer-1 gather-mean (fp32 x)
// ---------------------------------------------------------------------------
#define CVT_N_X   ((size_t)N_NODES * IN_DIM / 4)
#define CVT_N_W1  ((size_t)HID * IN_DIM / 4)
#define CVT_N_W2  ((size_t)OUT_DIM * HID / 4)
#define CVT_TOTAL (CVT_N_X + 2 * CVT_N_W1 + 2 * CVT_N_W2)
#define CVT_BLOCKS 2048
#define ZERO_BLOCKS 160
#define ZERO_N4 ((size_t)N_NODES * OUT_DIM / 4)   // per buffer

__global__ void prep_kernel(const float* __restrict__ x,   __nv_bfloat16* __restrict__ xb,
                            const float* __restrict__ w1l, __nv_bfloat16* __restrict__ w1lb,
                            const float* __restrict__ w1r, __nv_bfloat16* __restrict__ w1rb,
                            const float* __restrict__ w2l, __nv_bfloat16* __restrict__ w2lb,
                            const float* __restrict__ w2r, __nv_bfloat16* __restrict__ w2rb,
                            const int* __restrict__ rowptr, const int* __restrict__ csrc,
                            __nv_bfloat16* __restrict__ aggb,
                            float* __restrict__ outz, float* __restrict__ t2z) {
    if (blockIdx.x < CVT_BLOCKS) {
        size_t i = (size_t)blockIdx.x * blockDim.x + threadIdx.x;
        size_t stride = (size_t)CVT_BLOCKS * blockDim.x;
        for (; i < CVT_TOTAL; i += stride) {
            const float* s; __nv_bfloat16* d; size_t off = i;
            if (off < CVT_N_X) { s = x; d = xb; }
            else if ((off -= CVT_N_X) < CVT_N_W1) { s = w1l; d = w1lb; }
            else if ((off -= CVT_N_W1) < CVT_N_W1) { s = w1r; d = w1rb; }
            else if ((off -= CVT_N_W1) < CVT_N_W2) { s = w2l; d = w2lb; }
            else { off -= CVT_N_W2; s = w2r; d = w2rb; }
            float4 v = ((const float4*)s)[off];
            __nv_bfloat162* d2 = (__nv_bfloat162*)d + 2 * off;
            d2[0] = __floats2bfloat162_rn(v.x, v.y);
            d2[1] = __floats2bfloat162_rn(v.z, v.w);
        }
    } else if (blockIdx.x < CVT_BLOCKS + ZERO_BLOCKS) {
        size_t i = (size_t)(blockIdx.x - CVT_BLOCKS) * blockDim.x + threadIdx.x;
        size_t stride = (size_t)ZERO_BLOCKS * blockDim.x;
        float4 z = make_float4(0.f, 0.f, 0.f, 0.f);
        for (; i < ZERO_N4; i += stride) {
            ((float4*)outz)[i] = z;
            ((float4*)t2z)[i] = z;
        }
    } else {
        const int n = blockIdx.x - CVT_BLOCKS - ZERO_BLOCKS;
        const int t = threadIdx.x;
        const int beg = rowptr[n], end = rowptr[n + 1];
        float a0 = 0.f, a1 = 0.f, a2 = 0.f, a3 = 0.f;
        int j = beg;
        for (; j + 1 < end; j += 2) {
            int s0 = csrc[j], s1 = csrc[j + 1];
            float4 u0 = *(const float4*)(x + (size_t)s0 * IN_DIM + t * 4);
            float4 u1 = *(const float4*)(x + (size_t)s1 * IN_DIM + t * 4);
            a0 += u0.x + u1.x; a1 += u0.y + u1.y;
            a2 += u0.z + u1.z; a3 += u0.w + u1.w;
        }
        if (j < end) {
            float4 u0 = *(const float4*)(x + (size_t)csrc[j] * IN_DIM + t * 4);
            a0 += u0.x; a1 += u0.y; a2 += u0.z; a3 += u0.w;
        }
        float inv = 1.0f / fmaxf((float)(end - beg), 1.0f);
        __nv_bfloat162* o = (__nv_bfloat162*)(aggb + (size_t)n * IN_DIM + t * 4);
        o[0] = __floats2bfloat162_rn(a0 * inv, a1 * inv);
        o[1] = __floats2bfloat162_rn(a2 * inv, a3 * inv);
    }
}

// ---------------------------------------------------------------------------
// Final fused: gather-mean of t2 + add + log_softmax (shuffle reductions)
// ---------------------------------------------------------------------------
__global__ void final_kernel(float* __restrict__ out,
                             const float* __restrict__ t2,
                             const int* __restrict__ rowptr,
                             const int* __restrict__ csrc) {
    __shared__ float red[8];
    const int n = blockIdx.x;
    const int t = threadIdx.x;
    const int lane = t & 31, wq = t >> 5;
    const int beg = rowptr[n], end = rowptr[n + 1];

    float acc = 0.f;
    int j = beg;
    for (; j + 1 < end; j += 2) {
        int s0 = csrc[j], s1 = csrc[j + 1];
        acc += t2[(size_t)s0 * OUT_DIM + t] + t2[(size_t)s1 * OUT_DIM + t];
    }
    if (j < end) acc += t2[(size_t)csrc[j] * OUT_DIM + t];

    float inv = 1.0f / fmaxf((float)(end - beg), 1.0f);
    size_t idx = (size_t)n * OUT_DIM + t;
    float v = out[idx] + acc * inv;

    float m = v;
#pragma unroll
    for (int s = 16; s > 0; s >>= 1) m = fmaxf(m, __shfl_xor_sync(0xffffffffu, m, s));
    if (lane == 0) red[wq] = m;
    __syncthreads();
    m = red[lane & 7];
#pragma unroll
    for (int s = 4; s > 0; s >>= 1) m = fmaxf(m, __shfl_xor_sync(0xffffffffu, m, s));
    m = __shfl_sync(0xffffffffu, m, 0);

    float e = expf(v - m);
    float sum = e;
#pragma unroll
    for (int s = 16; s > 0; s >>= 1) sum += __shfl_xor_sync(0xffffffffu, sum, s);
    __syncthreads();
    if (lane == 0) red[wq] = sum;
    __syncthreads();
    sum = red[lane & 7];
#pragma unroll
    for (int s = 4; s > 0; s >>= 1) sum += __shfl_xor_sync(0xffffffffu, sum, s);
    sum = __shfl_sync(0xffffffffu, sum, 0);

    out[idx] = v - m - logf(sum);
}

// ---------------------------------------------------------------------------
// Launch
// ---------------------------------------------------------------------------
extern "C" void kernel_launch(void* const* d_in, const int* in_sizes, int n_in,
                              void* d_out, int out_size) {
    const float* x   = (const float*)d_in[0];
    const int*   ei  = (const int*)  d_in[1];
    const float* W1l = (const float*)d_in[2];
    const float* b1l = (const float*)d_in[3];
    const float* W1r = (const float*)d_in[4];
    const float* W2l = (const float*)d_in[5];
    const float* b2l = (const float*)d_in[6];
    const float* W2r = (const float*)d_in[7];
    float* out = (float*)d_out;

    const int* src = ei;
    const int* dst = ei + N_EDGES;

    float* t2;
    __nv_bfloat16 *agg1b, *xb, *h, *w1lb, *w1rb, *w2lb, *w2rb;
    int *deg, *rowptr, *pos, *csrc;
    cudaGetSymbolAddress((void**)&agg1b, g_agg1b);
    cudaGetSymbolAddress((void**)&xb,    g_xb);
    cudaGetSymbolAddress((void**)&h,     g_h);
    cudaGetSymbolAddress((void**)&t2,    g_t2);
    cudaGetSymbolAddress((void**)&w1lb,  g_w1lb);
    cudaGetSymbolAddress((void**)&w1rb,  g_w1rb);
    cudaGetSymbolAddress((void**)&w2lb,  g_w2lb);
    cudaGetSymbolAddress((void**)&w2rb,  g_w2rb);
    cudaGetSymbolAddress((void**)&deg,    g_deg);
    cudaGetSymbolAddress((void**)&rowptr, g_rowptr);
    cudaGetSymbolAddress((void**)&pos,    g_pos);
    cudaGetSymbolAddress((void**)&csrc,   g_csrc);

    cudaFuncSetAttribute(gemm_bf16_kernel<2, false, true, true, false>,
                         cudaFuncAttributeMaxDynamicSharedMemorySize, SMEM_BYTES);
    cudaFuncSetAttribute(gemm_bf16_kernel<1, true, false, false, true>,
                         cudaFuncAttributeMaxDynamicSharedMemorySize, SMEM_BYTES);

    // ---- CSR build (multi-kernel; R12 config) ----
    zero_int_kernel<<<(N_NODES + 255) / 256, 256>>>(deg, N_NODES);
    deg_kernel<<<(N_EDGES + 255) / 256, 256>>>(dst, deg);
    scan_kernel<<<1, 1024>>>(deg, rowptr, pos);
    fill_csr_kernel<<<(N_EDGES + 255) / 256, 256>>>(src, dst, pos, csrc);

    // ---- fused prep: converts + zero(out,t2) + layer-1 gather-mean ----
    prep_kernel<<<CVT_BLOCKS + ZERO_BLOCKS + N_NODES, 256>>>(
        x, xb, W1l, w1lb, W1r, w1rb, W2l, w2lb, W2r, w2rb, rowptr, csrc, agg1b,
        out, t2);

    // ---- layer 1: h(bf16) = relu(mean1@W1l^T + x@W1r^T + b1) ----
    {
        dim3 grid(HID / BN, (N_NODES + BM - 1) / BM);
        gemm_bf16_kernel<2, false, true, true, false><<<grid, 256, SMEM_BYTES>>>(
            agg1b, w1lb, xb, w1rb, h, nullptr, b1l, N_NODES, HID, IN_DIM);
    }

    // ---- layer 2 (split-N + split-K=2): out += h@W2r^T + b2 ; t2 += h@W2l^T ----
    {
        dim3 grid(2 * OUT_DIM / BN, (N_NODES + BM - 1) / BM, 2);
        gemm_bf16_kernel<1, true, false, false, true><<<grid, 256, SMEM_BYTES>>>(
            h, w2rb, nullptr, w2lb, out, t2, b2l, N_NODES, OUT_DIM, HID);
    }

    // ---- fused: out = log_softmax(out + mean_gather(t2)) ----
    final_kernel<<<N_NODES, 256>>>(out, t2, rowptr, csrc);
}

// round 17
// speedup vs baseline: 1.1026x; 1.0059x over previous
#include <cuda_runtime.h>
#include <cuda_bf16.h>
#include <math.h>
#include <stdint.h>

#define N_NODES 10000
#define N_EDGES 80000
#define IN_DIM  1024
#define HID     4096
#define OUT_DIM 256

// ---------------------------------------------------------------------------
// Scratch (device globals)
// ---------------------------------------------------------------------------
__device__ __align__(16) __nv_bfloat16 g_agg1b[(size_t)N_NODES * IN_DIM];   // 20 MB
__device__ __align__(16) __nv_bfloat16 g_xb[(size_t)N_NODES * IN_DIM];      // 20 MB
__device__ __align__(16) __nv_bfloat16 g_h[(size_t)N_NODES * HID];          // 80 MB
__device__ __align__(16) float g_t2[(size_t)N_NODES * OUT_DIM];             // 10 MB
__device__ __align__(16) __nv_bfloat16 g_w1lb[(size_t)HID * IN_DIM];        // 8 MB
__device__ __align__(16) __nv_bfloat16 g_w1rb[(size_t)HID * IN_DIM];        // 8 MB
__device__ __align__(16) __nv_bfloat16 g_w2lb[(size_t)OUT_DIM * HID];       // 2 MB
__device__ __align__(16) __nv_bfloat16 g_w2rb[(size_t)OUT_DIM * HID];       // 2 MB
// CSR
__device__ int g_deg[N_NODES];
__device__ int g_rowptr[N_NODES + 1];
__device__ int g_pos[N_NODES];
__device__ int g_csrc[N_EDGES];

// ---------------------------------------------------------------------------
// MMA / async-copy helpers
// ---------------------------------------------------------------------------
__device__ __forceinline__ void mma_bf16(float c[4],
        uint32_t a0, uint32_t a1, uint32_t a2, uint32_t a3,
        uint32_t b0, uint32_t b1) {
    asm volatile(
        "mma.sync.aligned.m16n8k16.row.col.f32.bf16.bf16.f32 "
        "{%0,%1,%2,%3},{%4,%5,%6,%7},{%8,%9},{%0,%1,%2,%3};"
        : "+f"(c[0]), "+f"(c[1]), "+f"(c[2]), "+f"(c[3])
        : "r"(a0), "r"(a1), "r"(a2), "r"(a3), "r"(b0), "r"(b1));
}
__device__ __forceinline__ void ldsm_x4(uint32_t r[4], uint32_t addr) {
    asm volatile("ldmatrix.sync.aligned.m8n8.x4.shared.b16 {%0,%1,%2,%3}, [%4];"
                 : "=r"(r[0]), "=r"(r[1]), "=r"(r[2]), "=r"(r[3]) : "r"(addr));
}
__device__ __forceinline__ void cp_async16(uint32_t smem, const void* g, bool valid) {
    int sz = valid ? 16 : 0;
    asm volatile("cp.async.cg.shared.global [%0], [%1], 16, %2;\n"
                 :: "r"(smem), "l"(g), "r"(sz));
}
__device__ __forceinline__ void cp_commit() { asm volatile("cp.async.commit_group;\n"); }
template<int W> __device__ __forceinline__ void cp_wait() {
    asm volatile("cp.async.wait_group %0;\n" :: "n"(W));
}

// ---------------------------------------------------------------------------
// BF16 tensor-core GEMM:  C[M,N] = A[M,K] @ W[N,K]^T   (A,W bf16; C fp32/bf16)
// BM=BN=128, BK=64, 256 threads = 8 warps (2m x 4n), warp tile 64x32,
// mma.sync.m16n8k16 + ldmatrix.x4, 3-stage cp.async ring, ONE sync/iter.
// smem rows 144 B (128 data + 16 pad): conflict-free ldmatrix (144%128=16).
//
// NPAIRS==2: C0 = relu(A0@W0^T + A1@W1^T + bias), stored bf16   (layer 1)
// SPLITN   : grid.x doubled: first half -> C0(fp32) = A0@W0^T + bias
//            second half -> C1(fp32) = A0@W1^T                  (layer 2)
// SK>1     : gridDim.z = SK; each z-slice covers K/SK; epilogue atomicAdd
//            into pre-zeroed fp32 C; bias added only by z==0.
// ---------------------------------------------------------------------------
#define BM 128
#define BN 128
#define BK 64
#define ROWB 144
#define STAGE_A (BM * ROWB)            // 18432
#define STAGE_AB (2 * STAGE_A)         // 36864 (A then B)
#define NSTAGE 3
#define SMEM_BYTES (NSTAGE * STAGE_AB) // 110592

__device__ __forceinline__ void load_tile(char* sA, char* sB,
        const __nv_bfloat16* __restrict__ A, const __nv_bfloat16* __restrict__ W,
        int M, int K, int row0, int col0, int k0, int tid) {
#pragma unroll
    for (int it = 0; it < 4; it++) {
        int c = tid + it * 256;
        int r = c >> 3, q = c & 7;
        bool okA = (row0 + r) < M;
        int ra = okA ? (row0 + r) : 0;
        uint32_t sa = (uint32_t)__cvta_generic_to_shared(sA + r * ROWB + q * 16);
        cp_async16(sa, A + (size_t)ra * K + k0 + q * 8, okA);
        uint32_t sb = (uint32_t)__cvta_generic_to_shared(sB + r * ROWB + q * 16);
        cp_async16(sb, W + (size_t)(col0 + r) * K + k0 + q * 8, true);
    }
    cp_commit();
}

template<int NPAIRS, bool SPLITN, bool RELU, bool CBF16, int SK>
__global__ __launch_bounds__(256, 2)
void gemm_bf16_kernel(const __nv_bfloat16* __restrict__ A0, const __nv_bfloat16* __restrict__ W0,
                      const __nv_bfloat16* __restrict__ A1, const __nv_bfloat16* __restrict__ W1,
                      void* __restrict__ C0v, void* __restrict__ C1v,
                      const float* __restrict__ bias,
                      int M, int N, int K) {
    extern __shared__ __align__(16) char smem[];

    const int tid = threadIdx.x;
    const int bx = blockIdx.x, by = blockIdx.y;

    const __nv_bfloat16* A = A0;
    const __nv_bfloat16* W = W0;
    void* Cv = C0v;
    bool useBias = (bias != nullptr);
    int col0;
    if (SPLITN) {
        int nHalf = N / BN;
        bool sel = bx >= nHalf;
        col0 = (sel ? bx - nHalf : bx) * BN;
        if (sel) { W = W1; Cv = C1v; useBias = false; }
    } else {
        col0 = bx * BN;
    }
    const int row0 = by * BM;

    const int Keff = (SK > 1) ? K / SK : K;
    const int koff = (SK > 1) ? blockIdx.z * Keff : 0;
    if (SK > 1 && blockIdx.z != 0) useBias = false;

    const int w  = tid >> 5, lane = tid & 31;
    const int wr = w >> 2;          // 0..1 -> m offset wr*64
    const int wc = w & 3;           // 0..3 -> n offset wc*32
    const int g  = lane >> 2;       // 0..7
    const int tg = lane & 3;        // 0..3

    const uint32_t aLane = (uint32_t)((lane & 15) * ROWB + (lane >> 4) * 16);
    const uint32_t bLane = (uint32_t)((((lane >> 4) * 8) + (lane & 7)) * ROWB + ((lane >> 3) & 1) * 16);
    const uint32_t sBase = (uint32_t)__cvta_generic_to_shared(smem);

    float acc[4][4][4];
#pragma unroll
    for (int mi = 0; mi < 4; mi++)
#pragma unroll
        for (int ni = 0; ni < 4; ni++)
#pragma unroll
            for (int q = 0; q < 4; q++) acc[mi][ni][q] = 0.f;

    const int stepsPerK = Keff / BK;
    const int nT = stepsPerK * NPAIRS;

    auto src_of = [&](int s, const __nv_bfloat16*& Ap, const __nv_bfloat16*& Wp, int& k0) {
        if (NPAIRS == 2 && s >= stepsPerK) { Ap = A1; Wp = W1; k0 = koff + (s - stepsPerK) * BK; }
        else { Ap = A; Wp = W; k0 = koff + s * BK; }
    };

    // prologue: issue loads for tiles 0 .. NSTAGE-2
#pragma unroll
    for (int s = 0; s < NSTAGE - 1; s++) {
        const __nv_bfloat16 *Ap, *Wp; int k0;
        src_of(s, Ap, Wp, k0);
        load_tile(smem + s * STAGE_AB, smem + s * STAGE_AB + STAGE_A,
                  Ap, Wp, M, K, row0, col0, k0, tid);
    }

    for (int t = 0; t < nT; t++) {
        const int buf = t % NSTAGE;
        if (t + 1 < nT) cp_wait<1>(); else cp_wait<0>();
        __syncthreads();
        if (t + NSTAGE - 1 < nT) {
            const __nv_bfloat16 *Ap, *Wp; int k0;
            src_of(t + NSTAGE - 1, Ap, Wp, k0);
            int nb = (t + NSTAGE - 1) % NSTAGE;
            load_tile(smem + nb * STAGE_AB, smem + nb * STAGE_AB + STAGE_A,
                      Ap, Wp, M, K, row0, col0, k0, tid);
        }

        const uint32_t aBase = sBase + buf * STAGE_AB;
        const uint32_t bBase = aBase + STAGE_A;
#pragma unroll
        for (int half = 0; half < 4; half++) {
            const uint32_t ks2 = half * 32;
            uint32_t a[4][4], b[2][4];
#pragma unroll
            for (int mi = 0; mi < 4; mi++)
                ldsm_x4(a[mi], aBase + (uint32_t)((wr * 64 + mi * 16) * ROWB) + aLane + ks2);
#pragma unroll
            for (int n2 = 0; n2 < 2; n2++)
                ldsm_x4(b[n2], bBase + (uint32_t)((wc * 32 + n2 * 16) * ROWB) + bLane + ks2);
#pragma unroll
            for (int mi = 0; mi < 4; mi++)
#pragma unroll
                for (int ni = 0; ni < 4; ni++)
                    mma_bf16(acc[mi][ni], a[mi][0], a[mi][1], a[mi][2], a[mi][3],
                             b[ni >> 1][(ni & 1) * 2], b[ni >> 1][(ni & 1) * 2 + 1]);
        }
    }

    // epilogue
#pragma unroll
    for (int mi = 0; mi < 4; mi++) {
        int rbase = row0 + wr * 64 + mi * 16 + g;
#pragma unroll
        for (int half = 0; half < 2; half++) {
            int r = rbase + half * 8;
            if (r < M) {
#pragma unroll
                for (int ni = 0; ni < 4; ni++) {
                    int c = col0 + wc * 32 + ni * 8 + 2 * tg;
                    float v0 = acc[mi][ni][half * 2 + 0];
                    float v1 = acc[mi][ni][half * 2 + 1];
                    if (useBias) { v0 += bias[c]; v1 += bias[c + 1]; }
                    if (RELU) { v0 = fmaxf(v0, 0.f); v1 = fmaxf(v1, 0.f); }
                    if (CBF16) {
                        __nv_bfloat16* crow = (__nv_bfloat16*)Cv + (size_t)r * N;
                        *(__nv_bfloat162*)(crow + c) = __floats2bfloat162_rn(v0, v1);
                    } else if (SK > 1) {
                        float* crow = (float*)Cv + (size_t)r * N;
                        atomicAdd(crow + c, v0);
                        atomicAdd(crow + c + 1, v1);
                    } else {
                        float* crow = (float*)Cv + (size_t)r * N;
                        *(float2*)(crow + c) = make_float2(v0, v1);
                    }
                }
            }
        }
    }
}

// ---------------------------------------------------------------------------
// CSR construction (multi-kernel; measured faster than single-block)
// ---------------------------------------------------------------------------
__global__ void zero_int_kernel(int* __restrict__ p, int n) {
    int i = blockIdx.x * blockDim.x + threadIdx.x;
    if (i < n) p[i] = 0;
}
__global__ void deg_kernel(const int* __restrict__ dst, int* __restrict__ deg) {
    int e = blockIdx.x * blockDim.x + threadIdx.x;
    if (e < N_EDGES) atomicAdd(&deg[dst[e]], 1);
}
__global__ void scan_kernel(const int* __restrict__ deg, int* __restrict__ rowptr,
                            int* __restrict__ pos) {
    __shared__ int part[1024];
    const int CH = 10;
    int t = threadIdx.x;
    int base = t * CH;
    int local[CH];
    int s = 0;
#pragma unroll
    for (int i = 0; i < CH; i++) {
        int idx = base + i;
        int d = (idx < N_NODES) ? deg[idx] : 0;
        local[i] = s;
        s += d;
    }
    part[t] = s;
    __syncthreads();
    for (int off = 1; off < 1024; off <<= 1) {
        int v = part[t];
        int u = (t >= off) ? part[t - off] : 0;
        __syncthreads();
        part[t] = v + u;
        __syncthreads();
    }
    int pre = (t == 0) ? 0 : part[t - 1];
#pragma unroll
    for (int i = 0; i < CH; i++) {
        int idx = base + i;
        if (idx < N_NODES) { rowptr[idx] = pre + local[i]; pos[idx] = pre + local[i]; }
    }
    if (t == 1023) rowptr[N_NODES] = part[1023];
}
__global__ void fill_csr_kernel(const int* __restrict__ src, const int* __restrict__ dst,
                                int* __restrict__ pos, int* __restrict__ csrc) {
    int e = blockIdx.x * blockDim.x + threadIdx.x;
    if (e < N_EDGES) {
        int slot = atomicAdd(&pos[dst[e]], 1);
        csrc[slot] = src[e];
    }
}

// ---------------------------------------------------------------------------
// cvt+zero kernel: fp32->bf16 converts (x + 4 weights) and zero of out/t2
// ---------------------------------------------------------------------------
#define CVT_N_X   ((size_t)N_NODES * IN_DIM / 4)
#define CVT_N_W1  ((size_t)HID * IN_DIM / 4)
#define CVT_N_W2  ((size_t)OUT_DIM * HID / 4)
#define CVT_TOTAL (CVT_N_X + 2 * CVT_N_W1 + 2 * CVT_N_W2)
#define CVT_BLOCKS 2048
#define ZERO_BLOCKS 160
#define ZERO_N4 ((size_t)N_NODES * OUT_DIM / 4)   // per buffer

__global__ void cvt_kernel(const float* __restrict__ x,   __nv_bfloat16* __restrict__ xb,
                           const float* __restrict__ w1l, __nv_bfloat16* __restrict__ w1lb,
                           const float* __restrict__ w1r, __nv_bfloat16* __restrict__ w1rb,
                           const float* __restrict__ w2l, __nv_bfloat16* __restrict__ w2lb,
                           const float* __restrict__ w2r, __nv_bfloat16* __restrict__ w2rb,
                           float* __restrict__ outz, float* __restrict__ t2z) {
    if (blockIdx.x < CVT_BLOCKS) {
        size_t i = (size_t)blockIdx.x * blockDim.x + threadIdx.x;
        size_t stride = (size_t)CVT_BLOCKS * blockDim.x;
        for (; i < CVT_TOTAL; i += stride) {
            const float* s; __nv_bfloat16* d; size_t off = i;
            if (off < CVT_N_X) { s = x; d = xb; }
            else if ((off -= CVT_N_X) < CVT_N_W1) { s = w1l; d = w1lb; }
            else if ((off -= CVT_N_W1) < CVT_N_W1) { s = w1r; d = w1rb; }
            else if ((off -= CVT_N_W1) < CVT_N_W2) { s = w2l; d = w2lb; }
            else { off -= CVT_N_W2; s = w2r; d = w2rb; }
            float4 v = ((const float4*)s)[off];
            __nv_bfloat162* d2 = (__nv_bfloat162*)d + 2 * off;
            d2[0] = __floats2bfloat162_rn(v.x, v.y);
            d2[1] = __floats2bfloat162_rn(v.z, v.w);
        }
    } else {
        size_t i = (size_t)(blockIdx.x - CVT_BLOCKS) * blockDim.x + threadIdx.x;
        size_t stride = (size_t)ZERO_BLOCKS * blockDim.x;
        float4 z = make_float4(0.f, 0.f, 0.f, 0.f);
        for (; i < ZERO_N4; i += stride) {
            ((float4*)outz)[i] = z;
            ((float4*)t2z)[i] = z;
        }
    }
}

// ---------------------------------------------------------------------------
// Gather-mean (layer 1) reading bf16 xb: half the read traffic of fp32 x.
// ---------------------------------------------------------------------------
__global__ void gather1_kernel(const __nv_bfloat16* __restrict__ xb,
                               const int* __restrict__ rowptr,
                               const int* __restrict__ csrc,
                               __nv_bfloat16* __restrict__ aggb) {
    const int n = blockIdx.x;
    const int t = threadIdx.x;
    const int beg = rowptr[n], end = rowptr[n + 1];
    float a0 = 0.f, a1 = 0.f, a2 = 0.f, a3 = 0.f;
    int j = beg;
    for (; j + 1 < end; j += 2) {
        int s0 = csrc[j], s1 = csrc[j + 1];
        uint2 u0 = *(const uint2*)(xb + (size_t)s0 * IN_DIM + t * 4);
        uint2 u1 = *(const uint2*)(xb + (size_t)s1 * IN_DIM + t * 4);
        __nv_bfloat162 p0 = *(__nv_bfloat162*)&u0.x, p1 = *(__nv_bfloat162*)&u0.y;
        __nv_bfloat162 q0 = *(__nv_bfloat162*)&u1.x, q1 = *(__nv_bfloat162*)&u1.y;
        a0 += __bfloat162float(p0.x) + __bfloat162float(q0.x);
        a1 += __bfloat162float(p0.y) + __bfloat162float(q0.y);
        a2 += __bfloat162float(p1.x) + __bfloat162float(q1.x);
        a3 += __bfloat162float(p1.y) + __bfloat162float(q1.y);
    }
    if (j < end) {
        uint2 u0 = *(const uint2*)(xb + (size_t)csrc[j] * IN_DIM + t * 4);
        __nv_bfloat162 p0 = *(__nv_bfloat162*)&u0.x, p1 = *(__nv_bfloat162*)&u0.y;
        a0 += __bfloat162float(p0.x);
        a1 += __bfloat162float(p0.y);
        a2 += __bfloat162float(p1.x);
        a3 += __bfloat162float(p1.y);
    }
    float inv = 1.0f / fmaxf((float)(end - beg), 1.0f);
    __nv_bfloat162* o = (__nv_bfloat162*)(aggb + (size_t)n * IN_DIM + t * 4);
    o[0] = __floats2bfloat162_rn(a0 * inv, a1 * inv);
    o[1] = __floats2bfloat162_rn(a2 * inv, a3 * inv);
}

// ---------------------------------------------------------------------------
// Final fused: gather-mean of t2 + add + log_softmax (shuffle reductions)
// ---------------------------------------------------------------------------
__global__ void final_kernel(float* __restrict__ out,
                             const float* __restrict__ t2,
                             const int* __restrict__ rowptr,
                             const int* __restrict__ csrc) {
    __shared__ float red[8];
    const int n = blockIdx.x;
    const int t = threadIdx.x;
    const int lane = t & 31, wq = t >> 5;
    const int beg = rowptr[n], end = rowptr[n + 1];

    float acc = 0.f;
    int j = beg;
    for (; j + 1 < end; j += 2) {
        int s0 = csrc[j], s1 = csrc[j + 1];
        acc += t2[(size_t)s0 * OUT_DIM + t] + t2[(size_t)s1 * OUT_DIM + t];
    }
    if (j < end) acc += t2[(size_t)csrc[j] * OUT_DIM + t];

    float inv = 1.0f / fmaxf((float)(end - beg), 1.0f);
    size_t idx = (size_t)n * OUT_DIM + t;
    float v = out[idx] + acc * inv;

    float m = v;
#pragma unroll
    for (int s = 16; s > 0; s >>= 1) m = fmaxf(m, __shfl_xor_sync(0xffffffffu, m, s));
    if (lane == 0) red[wq] = m;
    __syncthreads();
    m = red[lane & 7];
#pragma unroll
    for (int s = 4; s > 0; s >>= 1) m = fmaxf(m, __shfl_xor_sync(0xffffffffu, m, s));
    m = __shfl_sync(0xffffffffu, m, 0);

    float e = expf(v - m);
    float sum = e;
#pragma unroll
    for (int s = 16; s > 0; s >>= 1) sum += __shfl_xor_sync(0xffffffffu, sum, s);
    __syncthreads();
    if (lane == 0) red[wq] = sum;
    __syncthreads();
    sum = red[lane & 7];
#pragma unroll
    for (int s = 4; s > 0; s >>= 1) sum += __shfl_xor_sync(0xffffffffu, sum, s);
    sum = __shfl_sync(0xffffffffu, sum, 0);

    out[idx] = v - m - logf(sum);
}

// ---------------------------------------------------------------------------
// Launch
// ---------------------------------------------------------------------------
extern "C" void kernel_launch(void* const* d_in, const int* in_sizes, int n_in,
                              void* d_out, int out_size) {
    const float* x   = (const float*)d_in[0];
    const int*   ei  = (const int*)  d_in[1];
    const float* W1l = (const float*)d_in[2];
    const float* b1l = (const float*)d_in[3];
    const float* W1r = (const float*)d_in[4];
    const float* W2l = (const float*)d_in[5];
    const float* b2l = (const float*)d_in[6];
    const float* W2r = (const float*)d_in[7];
    float* out = (float*)d_out;

    const int* src = ei;
    const int* dst = ei + N_EDGES;

    float* t2;
    __nv_bfloat16 *agg1b, *xb, *h, *w1lb, *w1rb, *w2lb, *w2rb;
    int *deg, *rowptr, *pos, *csrc;
    cudaGetSymbolAddress((void**)&agg1b, g_agg1b);
    cudaGetSymbolAddress((void**)&xb,    g_xb);
    cudaGetSymbolAddress((void**)&h,     g_h);
    cudaGetSymbolAddress((void**)&t2,    g_t2);
    cudaGetSymbolAddress((void**)&w1lb,  g_w1lb);
    cudaGetSymbolAddress((void**)&w1rb,  g_w1rb);
    cudaGetSymbolAddress((void**)&w2lb,  g_w2lb);
    cudaGetSymbolAddress((void**)&w2rb,  g_w2rb);
    cudaGetSymbolAddress((void**)&deg,    g_deg);
    cudaGetSymbolAddress((void**)&rowptr, g_rowptr);
    cudaGetSymbolAddress((void**)&pos,    g_pos);
    cudaGetSymbolAddress((void**)&csrc,   g_csrc);

    cudaFuncSetAttribute(gemm_bf16_kernel<2, false, true, true, 1>,
                         cudaFuncAttributeMaxDynamicSharedMemorySize, SMEM_BYTES);
    cudaFuncSetAttribute(gemm_bf16_kernel<1, true, false, false, 4>,
                         cudaFuncAttributeMaxDynamicSharedMemorySize, SMEM_BYTES);

    // ---- CSR build (multi-kernel) ----
    zero_int_kernel<<<(N_NODES + 255) / 256, 256>>>(deg, N_NODES);
    deg_kernel<<<(N_EDGES + 255) / 256, 256>>>(dst, deg);
    scan_kernel<<<1, 1024>>>(deg, rowptr, pos);
    fill_csr_kernel<<<(N_EDGES + 255) / 256, 256>>>(src, dst, pos, csrc);

    // ---- converts + zero(out, t2) ----
    cvt_kernel<<<CVT_BLOCKS + ZERO_BLOCKS, 256>>>(
        x, xb, W1l, w1lb, W1r, w1rb, W2l, w2lb, W2r, w2rb, out, t2);

    // ---- layer-1 aggregation: gather-mean reading bf16 xb ----
    gather1_kernel<<<N_NODES, 256>>>(xb, rowptr, csrc, agg1b);

    // ---- layer 1: h(bf16) = relu(mean1@W1l^T + x@W1r^T + b1) ----
    {
        dim3 grid(HID / BN, (N_NODES + BM - 1) / BM);
        gemm_bf16_kernel<2, false, true, true, 1><<<grid, 256, SMEM_BYTES>>>(
            agg1b, w1lb, xb, w1rb, h, nullptr, b1l, N_NODES, HID, IN_DIM);
    }

    // ---- layer 2 (split-N + split-K=4): out += h@W2r^T + b2 ; t2 += h@W2l^T ----
    {
        dim3 grid(2 * OUT_DIM / BN, (N_NODES + BM - 1) / BM, 4);
        gemm_bf16_kernel<1, true, false, false, 4><<<grid, 256, SMEM_BYTES>>>(
            h, w2rb, nullptr, w2lb, out, t2, b2l, N_NODES, OUT_DIM, HID);
    }

    // ---- fused: out = log_softmax(out + mean_gather(t2)) ----
    final_kernel<<<N_NODES, 256>>>(out, t2, rowptr, csrc);
}